// round 1
// baseline (speedup 1.0000x reference)
#include <cuda_runtime.h>
#include <math.h>

// Problem constants
#define Bq 2
#define Sq 2048
#define Dq 512
#define Hq 8

// ---------------- scratch (device globals; no allocation allowed) ----------
__device__ float g_q[(size_t)Bq * Hq * Sq * Dq];      // 64 MB  [b,h,s,e]
__device__ float g_k[(size_t)Bq * Hq * Sq * Dq];      // 64 MB
__device__ float g_v[(size_t)Bq * Hq * Sq * Dq];      // 64 MB
__device__ float g_attn[(size_t)Bq * Hq * Sq * Sq];   // 256 MB [b,h,s,k]
__device__ float g_z[(size_t)Bq * Sq * Hq * Dq];      // 64 MB  [b,s,h,e] (concat layout)

// Batch-offset descriptor: offset(z) = (z / dv) * s1 + (z % md) * s2
struct Off {
    int dv; long s1; int md; long s2;
};

// ---------------------------------------------------------------------------
// Generic tiled SGEMM: C = alpha * A @ op(B) (+ bias), all row-major fp32.
// BT=false: op(B)=B [K,N].  BT=true: op(B)=B^T with B stored [N,K].
// Tile 128x128xBK8, 256 threads, 8x8 per thread. All dims multiples of 128/8.
// ---------------------------------------------------------------------------
template <bool BT>
__global__ void __launch_bounds__(256)
sgemm_kernel(const float* __restrict__ A, const float* __restrict__ Bm,
             float* __restrict__ C,
             int M, int N, int K, int lda, int ldb, int ldc,
             Off oa, Off ob, Off oc,
             float alpha, const float* __restrict__ bias)
{
    const int z = blockIdx.z;
    A  += (long)(z / oa.dv) * oa.s1 + (long)(z % oa.md) * oa.s2;
    Bm += (long)(z / ob.dv) * ob.s1 + (long)(z % ob.md) * ob.s2;
    C  += (long)(z / oc.dv) * oc.s1 + (long)(z % oc.md) * oc.s2;

    __shared__ float As[8][128];
    __shared__ float Bs[8][128];

    const int tid = threadIdx.x;
    const int tx = tid & 15;     // 0..15 -> N direction
    const int ty = tid >> 4;     // 0..15 -> M direction
    const int row0 = blockIdx.y * 128;
    const int col0 = blockIdx.x * 128;

    // global->shared load indices
    const int grow = tid >> 1;          // 0..127
    const int gcol = (tid & 1) * 4;     // 0 or 4
    const int brow = tid >> 5;          // 0..7   (NN)
    const int bcol = (tid & 31) * 4;    // 0..124 (NN)

    float acc[8][8];
    #pragma unroll
    for (int i = 0; i < 8; ++i)
        #pragma unroll
        for (int j = 0; j < 8; ++j) acc[i][j] = 0.0f;

    for (int k0 = 0; k0 < K; k0 += 8) {
        // A tile: [128 rows x 8 k]  (A row-major, contiguous in k)
        float4 av = *(const float4*)&A[(long)(row0 + grow) * lda + (k0 + gcol)];
        As[gcol + 0][grow] = av.x;
        As[gcol + 1][grow] = av.y;
        As[gcol + 2][grow] = av.z;
        As[gcol + 3][grow] = av.w;

        if (BT) {
            // B stored [N,K]: Bs[k][n] = B[n, k]
            float4 bv = *(const float4*)&Bm[(long)(col0 + grow) * ldb + (k0 + gcol)];
            Bs[gcol + 0][grow] = bv.x;
            Bs[gcol + 1][grow] = bv.y;
            Bs[gcol + 2][grow] = bv.z;
            Bs[gcol + 3][grow] = bv.w;
        } else {
            // B stored [K,N]: direct vectorized row copy
            *(float4*)&Bs[brow][bcol] =
                *(const float4*)&Bm[(long)(k0 + brow) * ldb + (col0 + bcol)];
        }
        __syncthreads();

        #pragma unroll
        for (int k = 0; k < 8; ++k) {
            float a[8], b[8];
            #pragma unroll
            for (int i = 0; i < 8; ++i) a[i] = As[k][ty * 8 + i];
            #pragma unroll
            for (int j = 0; j < 8; ++j) b[j] = Bs[k][tx * 8 + j];
            #pragma unroll
            for (int i = 0; i < 8; ++i)
                #pragma unroll
                for (int j = 0; j < 8; ++j)
                    acc[i][j] = fmaf(a[i], b[j], acc[i][j]);
        }
        __syncthreads();
    }

    #pragma unroll
    for (int i = 0; i < 8; ++i) {
        const long r = row0 + ty * 8 + i;
        #pragma unroll
        for (int j = 0; j < 8; j += 4) {
            const int c = col0 + tx * 8 + j;
            float4 v;
            v.x = acc[i][j + 0] * alpha;
            v.y = acc[i][j + 1] * alpha;
            v.z = acc[i][j + 2] * alpha;
            v.w = acc[i][j + 3] * alpha;
            if (bias) {
                v.x += bias[c + 0];
                v.y += bias[c + 1];
                v.z += bias[c + 2];
                v.w += bias[c + 3];
            }
            *(float4*)&C[r * ldc + c] = v;
        }
    }
}

// ---------------------------------------------------------------------------
// Row softmax over g_attn rows of length Sq. One block (256 thr) per row.
// ---------------------------------------------------------------------------
__global__ void __launch_bounds__(256) softmax_kernel()
{
    const long row = blockIdx.x;            // 0 .. B*H*S-1
    float* p = g_attn + row * (long)Sq;
    const int tid = threadIdx.x;

    float v[8];
    float mx = -1e30f;
    #pragma unroll
    for (int i = 0; i < 8; ++i) {
        v[i] = p[tid + i * 256];
        mx = fmaxf(mx, v[i]);
    }
    #pragma unroll
    for (int o = 16; o > 0; o >>= 1) mx = fmaxf(mx, __shfl_xor_sync(0xFFFFFFFFu, mx, o));

    __shared__ float sred[8];
    if ((tid & 31) == 0) sred[tid >> 5] = mx;
    __syncthreads();
    float m = sred[0];
    #pragma unroll
    for (int i = 1; i < 8; ++i) m = fmaxf(m, sred[i]);
    __syncthreads();

    float s = 0.0f;
    #pragma unroll
    for (int i = 0; i < 8; ++i) {
        v[i] = __expf(v[i] - m);
        s += v[i];
    }
    #pragma unroll
    for (int o = 16; o > 0; o >>= 1) s += __shfl_xor_sync(0xFFFFFFFFu, s, o);
    if ((tid & 31) == 0) sred[tid >> 5] = s;
    __syncthreads();
    float tot = 0.0f;
    #pragma unroll
    for (int i = 0; i < 8; ++i) tot += sred[i];

    const float inv = 1.0f / tot;
    #pragma unroll
    for (int i = 0; i < 8; ++i) p[tid + i * 256] = v[i] * inv;
}

// ---------------------------------------------------------------------------
// attn_avg[b,s,k] = mean_h attn[b,h,s,k]   (float4 per thread)
// ---------------------------------------------------------------------------
__global__ void __launch_bounds__(256) avg_kernel(float* __restrict__ out)
{
    const long idx = (long)blockIdx.x * 256 + threadIdx.x;   // float4 index
    const long per_b = (long)Sq * Sq / 4;
    const long b = idx / per_b;
    const long r = idx % per_b;

    const float4* base = (const float4*)g_attn;
    float4 acc = make_float4(0.f, 0.f, 0.f, 0.f);
    #pragma unroll
    for (int h = 0; h < Hq; ++h) {
        float4 t = base[(b * Hq + h) * per_b + r];
        acc.x += t.x; acc.y += t.y; acc.z += t.z; acc.w += t.w;
    }
    const float inv = 1.0f / Hq;
    acc.x *= inv; acc.y *= inv; acc.z *= inv; acc.w *= inv;
    ((float4*)out)[b * per_b + r] = acc;
}

// ---------------------------------------------------------------------------
extern "C" void kernel_launch(void* const* d_in, const int* in_sizes, int n_in,
                              void* d_out, int out_size)
{
    (void)in_sizes; (void)n_in; (void)out_size;

    const float* Xq = (const float*)d_in[0];
    const float* Xk = (const float*)d_in[1];
    const float* Xv = (const float*)d_in[2];
    const float* Wq = (const float*)d_in[3];
    const float* Wk = (const float*)d_in[4];
    const float* Wv = (const float*)d_in[5];
    const float* Wz = (const float*)d_in[6];
    const float* bz = (const float*)d_in[7];
    float* out = (float*)d_out;                          // [B,S,D]
    float* attn_avg = out + (long)Bq * Sq * Dq;          // [B,S,S]

    float *pq, *pk, *pv, *pattn, *pz;
    cudaGetSymbolAddress((void**)&pq, g_q);
    cudaGetSymbolAddress((void**)&pk, g_k);
    cudaGetSymbolAddress((void**)&pv, g_v);
    cudaGetSymbolAddress((void**)&pattn, g_attn);
    cudaGetSymbolAddress((void**)&pz, g_z);

    const long SD = (long)Sq * Dq;
    const long SS = (long)Sq * Sq;
    const long DD = (long)Dq * Dq;

    // --- QKV projections: per (b,h): [S,D] = X[b] @ W[h], 16 batches --------
    {
        dim3 grid(Dq / 128, Sq / 128, Bq * Hq);
        Off oa = { Hq, SD, 1, 0 };          // A = X[b]
        Off oc = { 1,  SD, 1, 0 };          // C = buf[z]
        Off obq = { 1, 0, Hq, DD };         // B = W[h]
        sgemm_kernel<false><<<grid, 256>>>(Xq, Wq, pq, Sq, Dq, Dq, Dq, Dq, Dq,
                                           oa, obq, oc, 1.0f, nullptr);
        sgemm_kernel<false><<<grid, 256>>>(Xk, Wk, pk, Sq, Dq, Dq, Dq, Dq, Dq,
                                           oa, obq, oc, 1.0f, nullptr);
        sgemm_kernel<false><<<grid, 256>>>(Xv, Wv, pv, Sq, Dq, Dq, Dq, Dq, Dq,
                                           oa, obq, oc, 1.0f, nullptr);
    }

    // --- scores: attn[z] = (1/sqrt(D)) * Q[z] @ K[z]^T -----------------------
    {
        dim3 grid(Sq / 128, Sq / 128, Bq * Hq);
        Off oa = { 1, SD, 1, 0 };
        Off ob = { 1, SD, 1, 0 };
        Off oc = { 1, SS, 1, 0 };
        const float scale = (float)(1.0 / sqrt((double)Dq));
        sgemm_kernel<true><<<grid, 256>>>(pq, pk, pattn, Sq, Sq, Dq, Dq, Dq, Sq,
                                          oa, ob, oc, scale, nullptr);
    }

    // --- softmax (in place) ---------------------------------------------------
    softmax_kernel<<<Bq * Hq * Sq, 256>>>();

    // --- head-average into output ----------------------------------------------
    avg_kernel<<<(Bq * SS / 4) / 256, 256>>>(attn_avg);

    // --- z[z] = attn[z] @ V[z], written in concat layout [b,s,h*D+e] ----------
    {
        dim3 grid(Dq / 128, Sq / 128, Bq * Hq);
        Off oa = { 1, SS, 1, 0 };
        Off ob = { 1, SD, 1, 0 };
        Off oc = { Hq, (long)Sq * Hq * Dq, Hq, Dq };
        sgemm_kernel<false><<<grid, 256>>>(pattn, pv, pz, Sq, Dq, Sq, Sq, Dq, Hq * Dq,
                                           oa, ob, oc, 1.0f, nullptr);
    }

    // --- out = zcat @ Wz + bz ---------------------------------------------------
    {
        dim3 grid(Dq / 128, (Bq * Sq) / 128, 1);
        Off oa = { 1, 0, 1, 0 };
        Off ob = { 1, 0, 1, 0 };
        Off oc = { 1, 0, 1, 0 };
        sgemm_kernel<false><<<grid, 256>>>(pz, Wz, out, Bq * Sq, Dq, Hq * Dq,
                                           Hq * Dq, Dq, Dq,
                                           oa, ob, oc, 1.0f, bz);
    }
}